// round 4
// baseline (speedup 1.0000x reference)
#include <cuda_runtime.h>

#define BB 8
#define NP 4096
#define KNN 20
#define ROWS (BB*NP)          // 32768
#define EDGES (ROWS*KNN)      // 655360

// ---------------- scratch (device globals; no allocations allowed) ----------
static __device__ float    g_negd[(size_t)BB * NP * NP];        // 512 MB
static __device__ int      g_idx[ROWS * KNN];
static __device__ float    g_hA[(size_t)EDGES * 64];            // 160 MB
static __device__ float    g_hB[(size_t)EDGES * 64];            // 160 MB
static __device__ float    g_x1[(size_t)ROWS * 64];
static __device__ float    g_x2[(size_t)ROWS * 64];
static __device__ float    g_x3[(size_t)ROWS * 64];
static __device__ float    g_cat[(size_t)ROWS * 192];
static __device__ float    g_h6[(size_t)ROWS * 1024];           // 128 MB
static __device__ unsigned g_gmaxEnc[BB * 1024];
static __device__ float    g_gterm[BB * 512];
static __device__ double   g_sum[8][1024];
static __device__ double   g_sqs[8][1024];
static __device__ float    g_scale[8][1024];
static __device__ float    g_shift[8][1024];
static __device__ float    g_W2t[64 * 64];
static __device__ float    g_W3t[128 * 64];
static __device__ float    g_W4t[64 * 64];
static __device__ float    g_W5t[128 * 64];

__device__ __forceinline__ float lrelu(float v) { return v > 0.f ? v : 0.2f * v; }
__device__ __forceinline__ unsigned fenc(float f) {
    unsigned u = __float_as_uint(f);
    return (u & 0x80000000u) ? ~u : (u | 0x80000000u);
}
__device__ __forceinline__ float fdec(unsigned u) {
    return (u & 0x80000000u) ? __uint_as_float(u & 0x7fffffffu) : __uint_as_float(~u);
}

// ---------------- zero stats/atomics (must run every replay) ----------------
__global__ void dg_zero_kernel() {
    int i = blockIdx.x * 256 + threadIdx.x;
    if (i < 8192) {
        (&g_sum[0][0])[i] = 0.0;
        (&g_sqs[0][0])[i] = 0.0;
        g_gmaxEnc[i] = 0u;
    }
}

// ---------------- transpose W2..W5 into Wt[c*64+o] --------------------------
__global__ void dg_prep_kernel(const float* W2, const float* W3,
                               const float* W4, const float* W5) {
    int i = blockIdx.x * 256 + threadIdx.x;
    if (i < 64 * 64)  { int o = i / 64,  c = i % 64;  g_W2t[c * 64 + o] = W2[i];
                                                      g_W4t[c * 64 + o] = W4[i]; }
    if (i < 64 * 128) { int o = i / 128, c = i % 128; g_W3t[c * 64 + o] = W3[i];
                                                      g_W5t[c * 64 + o] = W5[i]; }
}

// ---------------- kNN on raw xyz: cancellation-free distances ---------------
__global__ __launch_bounds__(256) void dg_knn_small(const float* __restrict__ x) {
    int q = blockIdx.x;
    int b = q >> 12, i = q & 4095;
    const float* xb = x + (size_t)b * 3 * NP;
    __shared__ float sd[NP];
    __shared__ float rv[8];
    __shared__ int   ri[8];
    int tid = threadIdx.x, lane = tid & 31, wid = tid >> 5;
    float qx = xb[i], qy = xb[NP + i], qz = xb[2 * NP + i];
    for (int j = tid; j < NP; j += 256) {
        float dx = xb[j] - qx, dy = xb[NP + j] - qy, dz = xb[2 * NP + j] - qz;
        sd[j] = -(dx * dx + dy * dy + dz * dz);
    }
    __syncthreads();
    for (int r = 0; r < KNN; r++) {
        float bv = -3.4e38f; int bi = 0x7fffffff;
        for (int j = tid; j < NP; j += 256) {
            float v = sd[j];
            if (v > bv) { bv = v; bi = j; }
        }
        for (int s = 16; s > 0; s >>= 1) {
            float ov = __shfl_xor_sync(0xffffffffu, bv, s);
            int   oi = __shfl_xor_sync(0xffffffffu, bi, s);
            if (ov > bv || (ov == bv && oi < bi)) { bv = ov; bi = oi; }
        }
        if (lane == 0) { rv[wid] = bv; ri[wid] = bi; }
        __syncthreads();
        if (tid == 0) {
            float bbv = rv[0]; int bbi = ri[0];
            for (int w = 1; w < 8; w++)
                if (rv[w] > bbv || (rv[w] == bbv && ri[w] < bbi)) { bbv = rv[w]; bbi = ri[w]; }
            g_idx[q * KNN + r] = bbi;
            sd[bbi] = -3.4e38f;
        }
        __syncthreads();
    }
}

// ---------------- top-k selection from a precomputed neg_d row --------------
__global__ __launch_bounds__(256) void dg_select_kernel() {
    int q = blockIdx.x;
    __shared__ float sd[NP];
    __shared__ float rv[8];
    __shared__ int   ri[8];
    const float* row = g_negd + (size_t)q * NP;
    int tid = threadIdx.x, lane = tid & 31, wid = tid >> 5;
    for (int j = tid; j < NP; j += 256) sd[j] = row[j];
    __syncthreads();
    for (int r = 0; r < KNN; r++) {
        float bv = -3.4e38f; int bi = 0x7fffffff;
        for (int j = tid; j < NP; j += 256) {
            float v = sd[j];
            if (v > bv) { bv = v; bi = j; }
        }
        for (int s = 16; s > 0; s >>= 1) {
            float ov = __shfl_xor_sync(0xffffffffu, bv, s);
            int   oi = __shfl_xor_sync(0xffffffffu, bi, s);
            if (ov > bv || (ov == bv && oi < bi)) { bv = ov; bi = oi; }
        }
        if (lane == 0) { rv[wid] = bv; ri[wid] = bi; }
        __syncthreads();
        if (tid == 0) {
            float bbv = rv[0]; int bbi = ri[0];
            for (int w = 1; w < 8; w++)
                if (rv[w] > bbv || (rv[w] == bbv && ri[w] < bbi)) { bbv = rv[w]; bbi = ri[w]; }
            g_idx[q * KNN + r] = bbi;
            sd[bbi] = -3.4e38f;
        }
        __syncthreads();
    }
}

// ---------------- pairwise -||a-b||^2 over 64-dim features -------------------
// neg_d[i][j] = -sum_c (A[i][c]-A[j][c])^2  (cancellation-free => ~true ranking)
__global__ __launch_bounds__(256) void dg_sqdist(const float* __restrict__ X,
                                                 float* __restrict__ C) {
    int bz = blockIdx.z;
    const float* A = X + (size_t)bz * NP * 64;
    float* Cb = C + (size_t)bz * NP * NP;
    __shared__ __align__(16) float As[64][68];
    __shared__ __align__(16) float Bs[64][68];
    int m0 = blockIdx.y * 64, n0 = blockIdx.x * 64;
    int tid = threadIdx.x, tx = tid & 15, ty = tid >> 4;
    // load full 64x64 tiles (K=64 fits)
    #pragma unroll
    for (int l = tid; l < 64 * 64; l += 256) {
        int r = l >> 6, c = l & 63;
        As[c][r] = A[(size_t)(m0 + r) * 64 + c];
        Bs[c][r] = A[(size_t)(n0 + r) * 64 + c];
    }
    __syncthreads();
    float acc[4][4] = {};
    #pragma unroll
    for (int k = 0; k < 64; k++) {
        float4 av = *(const float4*)&As[k][ty * 4];
        float4 bv = *(const float4*)&Bs[k][tx * 4];
        float a4[4] = {av.x, av.y, av.z, av.w};
        float b4[4] = {bv.x, bv.y, bv.z, bv.w};
        #pragma unroll
        for (int i = 0; i < 4; i++)
            #pragma unroll
            for (int j = 0; j < 4; j++) {
                float d = a4[i] - b4[j];
                acc[i][j] += d * d;
            }
    }
    int mBase = m0 + ty * 4, nBase = n0 + tx * 4;
    #pragma unroll
    for (int i = 0; i < 4; i++)
        #pragma unroll
        for (int j = 0; j < 4; j++)
            Cb[(size_t)(mBase + i) * NP + nBase + j] = -acc[i][j];
}

// ---------------- conv1: 6 -> 64 on gathered xyz edge features ---------------
__global__ __launch_bounds__(64) void dg_conv1(const float* __restrict__ x,
                                               const float* __restrict__ W1) {
    int q = blockIdx.x;
    int b = q >> 12, i = q & 4095;
    const float* xb = x + (size_t)b * 3 * NP;
    __shared__ float W1s[384];
    __shared__ float xi[3];
    int t = threadIdx.x;
    for (int l = t; l < 384; l += 64) W1s[l] = W1[l];
    if (t < 3) xi[t] = xb[t * NP + i];
    __syncthreads();
    float qx = xi[0], qy = xi[1], qz = xi[2];
    float w0 = W1s[t * 6 + 0], w1 = W1s[t * 6 + 1], w2 = W1s[t * 6 + 2];
    float w3 = W1s[t * 6 + 3], w4 = W1s[t * 6 + 4], w5 = W1s[t * 6 + 5];
    float sum = 0.f, sq = 0.f;
    for (int j = 0; j < KNN; j++) {
        int nb = g_idx[q * KNN + j];
        float nx = xb[nb], ny = xb[NP + nb], nz = xb[2 * NP + nb];
        float h = w0 * (nx - qx) + w1 * (ny - qy) + w2 * (nz - qz)
                + w3 * qx + w4 * qy + w5 * qz;
        g_hA[((size_t)q * KNN + j) * 64 + t] = h;
        sum += h; sq += h * h;
    }
    atomicAdd(&g_sum[0][t], (double)sum);
    atomicAdd(&g_sqs[0][t], (double)sq);
}

// ---------------- edge conv 64 -> 64 (applies bn+lrelu of sIn on input) ------
__global__ __launch_bounds__(64) void dg_conv_e64(const float* __restrict__ in,
                                                  float* __restrict__ out,
                                                  const float* __restrict__ Wt,
                                                  int sIn, int sOut) {
    int q = blockIdx.x, t = threadIdx.x;
    __shared__ float fS[64];
    float sc = g_scale[sIn][t], sh = g_shift[sIn][t];
    float sum = 0.f, sq = 0.f;
    for (int j = 0; j < KNN; j++) {
        size_t e = (size_t)q * KNN + j;
        float v = in[e * 64 + t];
        __syncthreads();
        fS[t] = lrelu(sc * v + sh);
        __syncthreads();
        float acc = 0.f;
        #pragma unroll 16
        for (int c = 0; c < 64; c++) acc += fS[c] * Wt[c * 64 + t];
        out[e * 64 + t] = acc;
        sum += acc; sq += acc * acc;
    }
    atomicAdd(&g_sum[sOut][t], (double)sum);
    atomicAdd(&g_sqs[sOut][t], (double)sq);
}

// ---------------- edge conv 128 -> 64 building [nbr - xi | xi] on the fly ----
__global__ __launch_bounds__(64) void dg_conv_e128(const float* __restrict__ xin,
                                                   float* __restrict__ out,
                                                   const float* __restrict__ Wt,
                                                   int sOut) {
    int q = blockIdx.x, t = threadIdx.x;
    int b = q >> 12;
    __shared__ float fS[128];
    float xi = xin[(size_t)q * 64 + t];
    float sum = 0.f, sq = 0.f;
    for (int j = 0; j < KNN; j++) {
        int nb = g_idx[q * KNN + j];
        float nv = xin[((size_t)(b * NP + nb)) * 64 + t];
        __syncthreads();
        fS[t]      = nv - xi;
        fS[64 + t] = xi;
        __syncthreads();
        float acc = 0.f;
        #pragma unroll 16
        for (int c = 0; c < 128; c++) acc += fS[c] * Wt[c * 64 + t];
        size_t e = (size_t)q * KNN + j;
        out[e * 64 + t] = acc;
        sum += acc; sq += acc * acc;
    }
    atomicAdd(&g_sum[sOut][t], (double)sum);
    atomicAdd(&g_sqs[sOut][t], (double)sq);
}

// ---------------- finalize BN: scale/shift from stats ------------------------
__global__ void dg_finalize(int stage, int C, double invCnt,
                            const float* __restrict__ g, const float* __restrict__ b) {
    int c = blockIdx.x * 256 + threadIdx.x;
    if (c >= C) return;
    double m = g_sum[stage][c] * invCnt;
    double v = g_sqs[stage][c] * invCnt - m * m;
    float sc = g[c] * rsqrtf((float)v + 1e-5f);
    g_scale[stage][c] = sc;
    g_shift[stage][c] = b[c] - (float)m * sc;
}

// ---------------- max over k neighbors (applies bn+lrelu) --------------------
__global__ __launch_bounds__(64) void dg_maxk(const float* __restrict__ hraw,
                                              float* __restrict__ xout, int stage) {
    int q = blockIdx.x, t = threadIdx.x;
    float s = g_scale[stage][t], sh = g_shift[stage][t];
    float m = -3.4e38f;
    for (int j = 0; j < KNN; j++) {
        float v = lrelu(hraw[((size_t)q * KNN + j) * 64 + t] * s + sh);
        m = fmaxf(m, v);
    }
    xout[(size_t)q * 64 + t] = m;
}

// ---------------- concat x1|x2|x3 --------------------------------------------
__global__ void dg_cat_kernel() {
    int i = blockIdx.x * 256 + threadIdx.x;
    if (i >= ROWS * 192) return;
    int r = i / 192, c = i % 192;
    float v = (c < 64)  ? g_x1[(size_t)r * 64 + c]
            : (c < 128) ? g_x2[(size_t)r * 64 + c - 64]
                        : g_x3[(size_t)r * 64 + c - 128];
    g_cat[i] = v;
}

// ---------------- generic tiled fp32 GEMM -----------------------------------
// C[m,n] = sum_k actA(A[m,k]) * W[n,k]   (+ modes)
// MODE bit0: apply bn(actStage)+lrelu to A loads
// MODE bit1: add g_gterm[(m/NPerBatch)*Nn + n]
#define GBM 64
#define GBN 64
#define GBK 32
template <int MODE>
__global__ __launch_bounds__(256) void dg_gemm(
    const float* __restrict__ A,
    const float* __restrict__ W, int ldw,
    float* __restrict__ C,
    int M, int Nn, int Kk, int actStage, int NPerBatch) {
    __shared__ __align__(16) float As[GBK][GBM + 4];
    __shared__ __align__(16) float Ws[GBK][GBN + 4];
    int m0 = blockIdx.y * GBM, n0 = blockIdx.x * GBN;
    int tid = threadIdx.x, tx = tid & 15, ty = tid >> 4;
    float acc[4][4] = {};
    for (int k0 = 0; k0 < Kk; k0 += GBK) {
        #pragma unroll
        for (int l = tid; l < GBM * GBK; l += 256) {
            int r = l >> 5, c = l & 31;
            float v = A[(size_t)(m0 + r) * Kk + k0 + c];
            if (MODE & 1) {
                int ch = k0 + c;
                v = lrelu(g_scale[actStage][ch] * v + g_shift[actStage][ch]);
            }
            As[c][r] = v;
        }
        #pragma unroll
        for (int l = tid; l < GBN * GBK; l += 256) {
            int r = l >> 5, c = l & 31;
            Ws[c][r] = W[(size_t)(n0 + r) * ldw + k0 + c];
        }
        __syncthreads();
        #pragma unroll
        for (int k = 0; k < GBK; k++) {
            float4 av = *(const float4*)&As[k][ty * 4];
            float4 bv = *(const float4*)&Ws[k][tx * 4];
            float a4[4] = {av.x, av.y, av.z, av.w};
            float b4[4] = {bv.x, bv.y, bv.z, bv.w};
            #pragma unroll
            for (int i = 0; i < 4; i++)
                #pragma unroll
                for (int j = 0; j < 4; j++)
                    acc[i][j] += a4[i] * b4[j];
        }
        __syncthreads();
    }
    int mBase = m0 + ty * 4, nBase = n0 + tx * 4;
    #pragma unroll
    for (int i = 0; i < 4; i++) {
        #pragma unroll
        for (int j = 0; j < 4; j++) {
            int m = mBase + i, n = nBase + j;
            float v = acc[i][j];
            if (MODE & 2) v += g_gterm[(m / NPerBatch) * Nn + n];
            C[(size_t)m * Nn + n] = v;
        }
    }
}

// ---------------- per-channel stats over [ROWS, C] ---------------------------
__global__ void dg_stats_point(const float* __restrict__ buf, int C, int stage) {
    int r0 = blockIdx.x * 128;
    for (int c = threadIdx.x; c < C; c += 256) {
        float s = 0.f, q = 0.f;
        for (int r = r0; r < r0 + 128; r++) {
            float v = buf[(size_t)r * C + c];
            s += v; q += v * v;
        }
        atomicAdd(&g_sum[stage][c], (double)s);
        atomicAdd(&g_sqs[stage][c], (double)q);
    }
}

// ---------------- global max pool over N (after bn6+lrelu) -------------------
__global__ __launch_bounds__(1024) void dg_gmax_kernel() {
    int b = blockIdx.y, chunk = blockIdx.x;
    int e = threadIdx.x;
    float s = g_scale[5][e], t = g_shift[5][e];
    float m = -3.4e38f;
    int n0 = chunk * 128;
    for (int n = n0; n < n0 + 128; n++) {
        float v = lrelu(s * g_h6[((size_t)(b * NP + n)) * 1024 + e] + t);
        m = fmaxf(m, v);
    }
    atomicMax(&g_gmaxEnc[b * 1024 + e], fenc(m));
}

// ---------------- gterm[b,o] = sum_e gmax[b,e] * W7[o,e] ---------------------
__global__ __launch_bounds__(512) void dg_gterm_kernel(const float* __restrict__ W7) {
    int b = blockIdx.x, o = threadIdx.x;
    float acc = 0.f;
    for (int e = 0; e < 1024; e++) {
        float v = fdec(g_gmaxEnc[b * 1024 + e]);
        acc += v * W7[(size_t)o * 1216 + e];
    }
    g_gterm[b * 512 + o] = acc;
}

// ---------------- final classifier: act8(h8) @ W9^T --------------------------
__global__ __launch_bounds__(288) void dg_final(const float* __restrict__ W9,
                                                float* __restrict__ out) {
    __shared__ float a[32 * 257];
    __shared__ float w[9 * 259];
    int tid = threadIdx.x;
    for (int l = tid; l < 2304; l += 288) {
        int o = l / 256, c = l % 256;
        w[o * 259 + c] = W9[l];
    }
    int r0 = blockIdx.x * 32;
    for (int l = tid; l < 32 * 256; l += 288) {
        int rr = l / 256, c = l % 256;
        float v = g_hB[(size_t)(r0 + rr) * 256 + c];
        a[rr * 257 + c] = lrelu(g_scale[7][c] * v + g_shift[7][c]);
    }
    __syncthreads();
    int rr = tid / 9, o = tid % 9;
    float acc = 0.f;
    #pragma unroll 16
    for (int c = 0; c < 256; c++) acc += a[rr * 257 + c] * w[o * 259 + c];
    out[(size_t)(r0 + rr) * 9 + o] = acc;
}

// ---------------- host orchestration -----------------------------------------
extern "C" void kernel_launch(void* const* d_in, const int* in_sizes, int n_in,
                              void* d_out, int out_size) {
    const float* x = (const float*)d_in[0];
    const float* W[10] = {0};
    const float* G[9] = {0};
    const float* Bp[9] = {0};
    if (n_in >= 27 && in_sizes[1] == 1) {
        // dict order: x, k, W1..W9, g1,b1..g8,b8
        for (int i = 1; i <= 9; i++) W[i] = (const float*)d_in[1 + i];
        for (int i = 1; i <= 8; i++) {
            G[i]  = (const float*)d_in[11 + 2 * (i - 1)];
            Bp[i] = (const float*)d_in[12 + 2 * (i - 1)];
        }
    } else {
        // signature order: x, W1..W9, g1,b1..g8,b8 (k last or absent)
        for (int i = 1; i <= 9; i++) W[i] = (const float*)d_in[i];
        for (int i = 1; i <= 8; i++) {
            G[i]  = (const float*)d_in[10 + 2 * (i - 1)];
            Bp[i] = (const float*)d_in[11 + 2 * (i - 1)];
        }
    }
    float* out = (float*)d_out;

    void* tmp;
    cudaGetSymbolAddress(&tmp, g_negd);  float* negd = (float*)tmp;
    cudaGetSymbolAddress(&tmp, g_hA);    float* hA   = (float*)tmp;
    cudaGetSymbolAddress(&tmp, g_hB);    float* hB   = (float*)tmp;
    cudaGetSymbolAddress(&tmp, g_x1);    float* x1   = (float*)tmp;
    cudaGetSymbolAddress(&tmp, g_x2);    float* x2   = (float*)tmp;
    cudaGetSymbolAddress(&tmp, g_x3);    float* x3   = (float*)tmp;
    cudaGetSymbolAddress(&tmp, g_cat);   float* cat  = (float*)tmp;
    cudaGetSymbolAddress(&tmp, g_h6);    float* h6   = (float*)tmp;
    cudaGetSymbolAddress(&tmp, g_W2t);   float* W2t  = (float*)tmp;
    cudaGetSymbolAddress(&tmp, g_W3t);   float* W3t  = (float*)tmp;
    cudaGetSymbolAddress(&tmp, g_W4t);   float* W4t  = (float*)tmp;
    cudaGetSymbolAddress(&tmp, g_W5t);   float* W5t  = (float*)tmp;

    const double invE = 1.0 / (double)EDGES;
    const double invR = 1.0 / (double)ROWS;

    dg_zero_kernel<<<32, 256>>>();
    dg_prep_kernel<<<32, 256>>>(W[2], W[3], W[4], W[5]);

    // ---- block 1 (xyz) ----
    dg_knn_small<<<ROWS, 256>>>(x);
    dg_conv1<<<ROWS, 64>>>(x, W[1]);
    dg_finalize<<<1, 256>>>(0, 64, invE, G[1], Bp[1]);
    dg_conv_e64<<<ROWS, 64>>>(hA, hB, W2t, 0, 1);
    dg_finalize<<<1, 256>>>(1, 64, invE, G[2], Bp[2]);
    dg_maxk<<<ROWS, 64>>>(hB, x1, 1);

    // ---- block 2 (x1) ----
    dg_sqdist<<<dim3(NP / 64, NP / 64, BB), 256>>>(x1, negd);
    dg_select_kernel<<<ROWS, 256>>>();
    dg_conv_e128<<<ROWS, 64>>>(x1, hA, W3t, 2);
    dg_finalize<<<1, 256>>>(2, 64, invE, G[3], Bp[3]);
    dg_conv_e64<<<ROWS, 64>>>(hA, hB, W4t, 2, 3);
    dg_finalize<<<1, 256>>>(3, 64, invE, G[4], Bp[4]);
    dg_maxk<<<ROWS, 64>>>(hB, x2, 3);

    // ---- block 3 (x2) ----
    dg_sqdist<<<dim3(NP / 64, NP / 64, BB), 256>>>(x2, negd);
    dg_select_kernel<<<ROWS, 256>>>();
    dg_conv_e128<<<ROWS, 64>>>(x2, hA, W5t, 4);
    dg_finalize<<<1, 256>>>(4, 64, invE, G[5], Bp[5]);
    dg_maxk<<<ROWS, 64>>>(hA, x3, 4);

    // ---- point MLPs ----
    dg_cat_kernel<<<(ROWS * 192 + 255) / 256, 256>>>();
    dg_gemm<0><<<dim3(1024 / 64, ROWS / 64, 1), 256>>>(
        cat, W[6], 192, h6, ROWS, 1024, 192, -1, NP);
    dg_stats_point<<<256, 256>>>(h6, 1024, 5);
    dg_finalize<<<4, 256>>>(5, 1024, invR, G[6], Bp[6]);
    dg_gmax_kernel<<<dim3(32, BB), 1024>>>();
    dg_gterm_kernel<<<BB, 512>>>(W[7]);
    dg_gemm<2><<<dim3(512 / 64, ROWS / 64, 1), 256>>>(
        cat, W[7] + 1024, 1216, hA, ROWS, 512, 192, -1, NP);
    dg_stats_point<<<256, 256>>>(hA, 512, 6);
    dg_finalize<<<2, 256>>>(6, 512, invR, G[7], Bp[7]);
    dg_gemm<1><<<dim3(256 / 64, ROWS / 64, 1), 256>>>(
        hA, W[8], 512, hB, ROWS, 256, 512, 6, NP);
    dg_stats_point<<<256, 256>>>(hB, 256, 7);
    dg_finalize<<<1, 256>>>(7, 256, invR, G[8], Bp[8]);
    dg_final<<<ROWS / 32, 288>>>(W[9], out);
}

// round 7
// speedup vs baseline: 1.3266x; 1.3266x over previous
#include <cuda_runtime.h>

#define BB 8
#define NP 4096
#define KNN 20
#define ROWS (BB*NP)          // 32768
#define EDGES (ROWS*KNN)      // 655360

// ---------------- scratch (device globals; no allocations allowed) ----------
static __device__ float    g_negd[(size_t)BB * NP * NP];        // 512 MB
static __device__ int      g_idx[ROWS * KNN];
static __device__ float    g_hA[(size_t)EDGES * 64];            // 160 MB
static __device__ float    g_hB[(size_t)EDGES * 64];            // 160 MB
static __device__ float    g_x1[(size_t)ROWS * 64];
static __device__ float    g_x2[(size_t)ROWS * 64];
static __device__ float    g_x3[(size_t)ROWS * 64];
static __device__ float    g_cat[(size_t)ROWS * 192];
static __device__ float    g_h6[(size_t)ROWS * 1024];           // 128 MB
static __device__ unsigned g_gmaxEnc[BB * 1024];
static __device__ float    g_gterm[BB * 512];
static __device__ double   g_sum[8][1024];
static __device__ double   g_sqs[8][1024];
static __device__ float    g_scale[8][1024];
static __device__ float    g_shift[8][1024];

__device__ __forceinline__ float lrelu(float v) { return v > 0.f ? v : 0.2f * v; }
__device__ __forceinline__ unsigned fenc(float f) {
    unsigned u = __float_as_uint(f);
    return (u & 0x80000000u) ? ~u : (u | 0x80000000u);
}
__device__ __forceinline__ float fdec(unsigned u) {
    return (u & 0x80000000u) ? __uint_as_float(u & 0x7fffffffu) : __uint_as_float(~u);
}

extern __shared__ float dsm[];

// ---------------- zero stats/atomics (must run every replay) ----------------
__global__ void dg_zero_kernel() {
    int i = blockIdx.x * 256 + threadIdx.x;
    if (i < 8192) {
        (&g_sum[0][0])[i] = 0.0;
        (&g_sqs[0][0])[i] = 0.0;
        g_gmaxEnc[i] = 0u;
    }
}

// ---------------- kNN on raw xyz: cancellation-free distances ---------------
__global__ __launch_bounds__(256) void dg_knn_small(const float* __restrict__ x) {
    int q = blockIdx.x;
    int b = q >> 12, i = q & 4095;
    const float* xb = x + (size_t)b * 3 * NP;
    __shared__ float sd[NP];
    __shared__ float rv[8];
    __shared__ int   ri[8];
    int tid = threadIdx.x, lane = tid & 31, wid = tid >> 5;
    float qx = xb[i], qy = xb[NP + i], qz = xb[2 * NP + i];
    for (int j = tid; j < NP; j += 256) {
        float dx = xb[j] - qx, dy = xb[NP + j] - qy, dz = xb[2 * NP + j] - qz;
        sd[j] = -(dx * dx + dy * dy + dz * dz);
    }
    __syncthreads();
    for (int r = 0; r < KNN; r++) {
        float bv = -3.4e38f; int bi = 0x7fffffff;
        for (int j = tid; j < NP; j += 256) {
            float v = sd[j];
            if (v > bv) { bv = v; bi = j; }
        }
        for (int s = 16; s > 0; s >>= 1) {
            float ov = __shfl_xor_sync(0xffffffffu, bv, s);
            int   oi = __shfl_xor_sync(0xffffffffu, bi, s);
            if (ov > bv || (ov == bv && oi < bi)) { bv = ov; bi = oi; }
        }
        if (lane == 0) { rv[wid] = bv; ri[wid] = bi; }
        __syncthreads();
        if (tid == 0) {
            float bbv = rv[0]; int bbi = ri[0];
            for (int w = 1; w < 8; w++)
                if (rv[w] > bbv || (rv[w] == bbv && ri[w] < bbi)) { bbv = rv[w]; bbi = ri[w]; }
            g_idx[q * KNN + r] = bbi;
            sd[bbi] = -3.4e38f;
        }
        __syncthreads();
    }
}

// ---------------- top-k selection from a precomputed neg_d row --------------
__global__ __launch_bounds__(256) void dg_select_kernel() {
    int q = blockIdx.x;
    __shared__ float sd[NP];
    __shared__ float rv[8];
    __shared__ int   ri[8];
    const float* row = g_negd + (size_t)q * NP;
    int tid = threadIdx.x, lane = tid & 31, wid = tid >> 5;
    for (int j = tid; j < NP; j += 256) sd[j] = row[j];
    __syncthreads();
    for (int r = 0; r < KNN; r++) {
        float bv = -3.4e38f; int bi = 0x7fffffff;
        for (int j = tid; j < NP; j += 256) {
            float v = sd[j];
            if (v > bv) { bv = v; bi = j; }
        }
        for (int s = 16; s > 0; s >>= 1) {
            float ov = __shfl_xor_sync(0xffffffffu, bv, s);
            int   oi = __shfl_xor_sync(0xffffffffu, bi, s);
            if (ov > bv || (ov == bv && oi < bi)) { bv = ov; bi = oi; }
        }
        if (lane == 0) { rv[wid] = bv; ri[wid] = bi; }
        __syncthreads();
        if (tid == 0) {
            float bbv = rv[0]; int bbi = ri[0];
            for (int w = 1; w < 8; w++)
                if (rv[w] > bbv || (rv[w] == bbv && ri[w] < bbi)) { bbv = rv[w]; bbi = ri[w]; }
            g_idx[q * KNN + r] = bbi;
            sd[bbi] = -3.4e38f;
        }
        __syncthreads();
    }
}

// ---------------- pairwise -||a-b||^2, 128x128 tile, 8x8 per thread ----------
__global__ __launch_bounds__(256) void dg_sqdist128(const float* __restrict__ X,
                                                    float* __restrict__ C) {
    int bz = blockIdx.z;
    const float* A = X + (size_t)bz * NP * 64;
    float* Cb = C + (size_t)bz * NP * NP;
    float* As = dsm;              // [64][132]
    float* Bs = dsm + 64 * 132;   // [64][132]
    int m0 = blockIdx.y * 128, n0 = blockIdx.x * 128;
    int tid = threadIdx.x;
    {
        int r = tid >> 1, cb = (tid & 1) * 32;
        const float4* pa = (const float4*)(A + (size_t)(m0 + r) * 64 + cb);
        const float4* pb = (const float4*)(A + (size_t)(n0 + r) * 64 + cb);
        #pragma unroll
        for (int i = 0; i < 8; i++) {
            float4 va = pa[i], vb = pb[i];
            int c = cb + i * 4;
            As[(c+0)*132 + r] = va.x; As[(c+1)*132 + r] = va.y;
            As[(c+2)*132 + r] = va.z; As[(c+3)*132 + r] = va.w;
            Bs[(c+0)*132 + r] = vb.x; Bs[(c+1)*132 + r] = vb.y;
            Bs[(c+2)*132 + r] = vb.z; Bs[(c+3)*132 + r] = vb.w;
        }
    }
    __syncthreads();
    int tx = tid & 15, ty = tid >> 4;
    float acc[8][8] = {};
    #pragma unroll 8
    for (int k = 0; k < 64; k++) {
        float a[8], b[8];
        float4 a0 = *(const float4*)&As[k*132 + ty*8];
        float4 a1 = *(const float4*)&As[k*132 + ty*8 + 4];
        float4 b0 = *(const float4*)&Bs[k*132 + tx*8];
        float4 b1 = *(const float4*)&Bs[k*132 + tx*8 + 4];
        a[0]=a0.x; a[1]=a0.y; a[2]=a0.z; a[3]=a0.w;
        a[4]=a1.x; a[5]=a1.y; a[6]=a1.z; a[7]=a1.w;
        b[0]=b0.x; b[1]=b0.y; b[2]=b0.z; b[3]=b0.w;
        b[4]=b1.x; b[5]=b1.y; b[6]=b1.z; b[7]=b1.w;
        #pragma unroll
        for (int i = 0; i < 8; i++)
            #pragma unroll
            for (int j = 0; j < 8; j++) {
                float d = a[i] - b[j];
                acc[i][j] += d * d;
            }
    }
    #pragma unroll
    for (int i = 0; i < 8; i++) {
        size_t rowOff = (size_t)(m0 + ty*8 + i) * NP + n0 + tx*8;
        *(float4*)&Cb[rowOff]     = make_float4(-acc[i][0], -acc[i][1], -acc[i][2], -acc[i][3]);
        *(float4*)&Cb[rowOff + 4] = make_float4(-acc[i][4], -acc[i][5], -acc[i][6], -acc[i][7]);
    }
}

// ---------------- conv1 as gather-GEMM: 128 edges x 64 out, K=6 -------------
__global__ __launch_bounds__(256) void dg_conv1e(const float* __restrict__ x,
                                                 const float* __restrict__ W1,
                                                 float* __restrict__ out) {
    __shared__ float fS[6 * 132];
    __shared__ float Ws[6 * 68];
    __shared__ int qS[128], nbS[128];
    __shared__ float redS[1024], redQ[1024];
    int e0 = blockIdx.x * 128;
    int tid = threadIdx.x;
    if (tid < 128) { int e = e0 + tid; qS[tid] = e / KNN; nbS[tid] = g_idx[e]; }
    for (int l = tid; l < 384; l += 256) {
        int o = l / 6, c = l % 6;
        Ws[c * 68 + o] = W1[l];
    }
    __syncthreads();
    for (int l = tid; l < 1024; l += 256) {       // FIXED: 128 rows x 8 slots
        int r = l >> 3, c = l & 7;
        if (c < 6) {
            int q = qS[r], nb = nbS[r];
            const float* xb = x + (size_t)(q >> 12) * 3 * NP;
            int qi = q & 4095;
            float v = (c < 3) ? (xb[c * NP + nb] - xb[c * NP + qi])
                              : xb[(c - 3) * NP + qi];
            fS[c * 132 + r] = v;
        }
    }
    __syncthreads();
    int tx = tid & 15, ty = tid >> 4;
    float acc[8][4] = {};
    #pragma unroll
    for (int k = 0; k < 6; k++) {
        float a[8], b[4];
        #pragma unroll
        for (int i = 0; i < 8; i++) a[i] = fS[k*132 + ty*8 + i];
        float4 bv = *(const float4*)&Ws[k*68 + tx*4];
        b[0]=bv.x; b[1]=bv.y; b[2]=bv.z; b[3]=bv.w;
        #pragma unroll
        for (int i = 0; i < 8; i++)
            #pragma unroll
            for (int j = 0; j < 4; j++)
                acc[i][j] += a[i] * b[j];
    }
    float s[4] = {}, sq[4] = {};
    #pragma unroll
    for (int i = 0; i < 8; i++) {
        size_t rowOff = (size_t)(e0 + ty*8 + i) * 64 + tx*4;
        *(float4*)&out[rowOff] = make_float4(acc[i][0], acc[i][1], acc[i][2], acc[i][3]);
        #pragma unroll
        for (int j = 0; j < 4; j++) { s[j] += acc[i][j]; sq[j] += acc[i][j]*acc[i][j]; }
    }
    #pragma unroll
    for (int j = 0; j < 4; j++) { redS[ty*64 + tx*4 + j] = s[j]; redQ[ty*64 + tx*4 + j] = sq[j]; }
    __syncthreads();
    if (tid < 64) {
        float S = 0.f, Q = 0.f;
        #pragma unroll
        for (int t = 0; t < 16; t++) { S += redS[t*64 + tid]; Q += redQ[t*64 + tid]; }
        atomicAdd(&g_sum[0][tid], (double)S);
        atomicAdd(&g_sqs[0][tid], (double)Q);
    }
}

// ---------------- edge conv 64 -> 64 as GEMM (act fused into A load) ---------
__global__ __launch_bounds__(256) void dg_econv64(const float* __restrict__ in,
                                                  float* __restrict__ out,
                                                  const float* __restrict__ W,
                                                  int sIn, int sOut) {
    float* fS = dsm;              // [64][132]
    float* Ws = dsm + 64 * 132;   // [64][68]
    __shared__ float scS[64], shS[64];
    int e0 = blockIdx.x * 128;
    int tid = threadIdx.x;
    if (tid < 64) { scS[tid] = g_scale[sIn][tid]; shS[tid] = g_shift[sIn][tid]; }
    for (int l = tid; l < 4096; l += 256) {
        int c = l >> 6, n = l & 63;
        Ws[c * 68 + n] = W[n * 64 + c];
    }
    __syncthreads();
    {
        int r = tid >> 1, cb = (tid & 1) * 32;
        const float4* p = (const float4*)(in + (size_t)(e0 + r) * 64 + cb);
        #pragma unroll
        for (int i = 0; i < 8; i++) {
            float4 v = p[i];
            int c = cb + i * 4;
            fS[(c+0)*132 + r] = lrelu(scS[c+0]*v.x + shS[c+0]);
            fS[(c+1)*132 + r] = lrelu(scS[c+1]*v.y + shS[c+1]);
            fS[(c+2)*132 + r] = lrelu(scS[c+2]*v.z + shS[c+2]);
            fS[(c+3)*132 + r] = lrelu(scS[c+3]*v.w + shS[c+3]);
        }
    }
    __syncthreads();
    int tx = tid & 15, ty = tid >> 4;
    float acc[8][4] = {};
    #pragma unroll 8
    for (int k = 0; k < 64; k++) {
        float a[8], b[4];
        float4 a0 = *(const float4*)&fS[k*132 + ty*8];
        float4 a1 = *(const float4*)&fS[k*132 + ty*8 + 4];
        float4 bv = *(const float4*)&Ws[k*68 + tx*4];
        a[0]=a0.x; a[1]=a0.y; a[2]=a0.z; a[3]=a0.w;
        a[4]=a1.x; a[5]=a1.y; a[6]=a1.z; a[7]=a1.w;
        b[0]=bv.x; b[1]=bv.y; b[2]=bv.z; b[3]=bv.w;
        #pragma unroll
        for (int i = 0; i < 8; i++)
            #pragma unroll
            for (int j = 0; j < 4; j++)
                acc[i][j] += a[i] * b[j];
    }
    float s[4] = {}, sq[4] = {};
    #pragma unroll
    for (int i = 0; i < 8; i++) {
        size_t rowOff = (size_t)(e0 + ty*8 + i) * 64 + tx*4;
        *(float4*)&out[rowOff] = make_float4(acc[i][0], acc[i][1], acc[i][2], acc[i][3]);
        #pragma unroll
        for (int j = 0; j < 4; j++) { s[j] += acc[i][j]; sq[j] += acc[i][j]*acc[i][j]; }
    }
    __syncthreads();
    float* redS = fS;
    float* redQ = fS + 1024;
    #pragma unroll
    for (int j = 0; j < 4; j++) { redS[ty*64 + tx*4 + j] = s[j]; redQ[ty*64 + tx*4 + j] = sq[j]; }
    __syncthreads();
    if (tid < 64) {
        float S = 0.f, Q = 0.f;
        #pragma unroll
        for (int t = 0; t < 16; t++) { S += redS[t*64 + tid]; Q += redQ[t*64 + tid]; }
        atomicAdd(&g_sum[sOut][tid], (double)S);
        atomicAdd(&g_sqs[sOut][tid], (double)Q);
    }
}

// ---------------- edge conv 128 -> 64 as GEMM with on-the-fly gather ---------
__global__ __launch_bounds__(256) void dg_econv128(const float* __restrict__ xin,
                                                   float* __restrict__ out,
                                                   const float* __restrict__ W,
                                                   int sOut) {
    float* fS = dsm;              // [64][132]
    float* Ws = dsm + 64 * 132;   // [64][68]
    __shared__ int qS[128], nbS[128];
    int e0 = blockIdx.x * 128;
    int tid = threadIdx.x;
    if (tid < 128) {
        int e = e0 + tid;
        int q = e / KNN;
        qS[tid] = q;
        nbS[tid] = (q >> 12) * NP + g_idx[e];   // global neighbor row
    }
    __syncthreads();
    int tx = tid & 15, ty = tid >> 4;
    float acc[8][4] = {};
    for (int kt = 0; kt < 2; kt++) {
        int r = tid >> 1, cb = (tid & 1) * 32;
        int q = qS[r];
        const float4* pq = (const float4*)(xin + (size_t)q * 64 + cb);
        if (kt == 0) {
            const float4* pn = (const float4*)(xin + (size_t)nbS[r] * 64 + cb);
            #pragma unroll
            for (int i = 0; i < 8; i++) {
                float4 vn = pn[i], vq = pq[i];
                int c = cb + i * 4;
                fS[(c+0)*132 + r] = vn.x - vq.x;
                fS[(c+1)*132 + r] = vn.y - vq.y;
                fS[(c+2)*132 + r] = vn.z - vq.z;
                fS[(c+3)*132 + r] = vn.w - vq.w;
            }
        } else {
            #pragma unroll
            for (int i = 0; i < 8; i++) {
                float4 vq = pq[i];
                int c = cb + i * 4;
                fS[(c+0)*132 + r] = vq.x;
                fS[(c+1)*132 + r] = vq.y;
                fS[(c+2)*132 + r] = vq.z;
                fS[(c+3)*132 + r] = vq.w;
            }
        }
        for (int l = tid; l < 4096; l += 256) {
            int c = l >> 6, n = l & 63;
            Ws[c * 68 + n] = W[n * 128 + kt * 64 + c];
        }
        __syncthreads();
        #pragma unroll 8
        for (int k = 0; k < 64; k++) {
            float a[8], b[4];
            float4 a0 = *(const float4*)&fS[k*132 + ty*8];
            float4 a1 = *(const float4*)&fS[k*132 + ty*8 + 4];
            float4 bv = *(const float4*)&Ws[k*68 + tx*4];
            a[0]=a0.x; a[1]=a0.y; a[2]=a0.z; a[3]=a0.w;
            a[4]=a1.x; a[5]=a1.y; a[6]=a1.z; a[7]=a1.w;
            b[0]=bv.x; b[1]=bv.y; b[2]=bv.z; b[3]=bv.w;
            #pragma unroll
            for (int i = 0; i < 8; i++)
                #pragma unroll
                for (int j = 0; j < 4; j++)
                    acc[i][j] += a[i] * b[j];
        }
        __syncthreads();
    }
    float s[4] = {}, sq[4] = {};
    #pragma unroll
    for (int i = 0; i < 8; i++) {
        size_t rowOff = (size_t)(e0 + ty*8 + i) * 64 + tx*4;
        *(float4*)&out[rowOff] = make_float4(acc[i][0], acc[i][1], acc[i][2], acc[i][3]);
        #pragma unroll
        for (int j = 0; j < 4; j++) { s[j] += acc[i][j]; sq[j] += acc[i][j]*acc[i][j]; }
    }
    float* redS = fS;
    float* redQ = fS + 1024;
    #pragma unroll
    for (int j = 0; j < 4; j++) { redS[ty*64 + tx*4 + j] = s[j]; redQ[ty*64 + tx*4 + j] = sq[j]; }
    __syncthreads();
    if (tid < 64) {
        float S = 0.f, Q = 0.f;
        #pragma unroll
        for (int t = 0; t < 16; t++) { S += redS[t*64 + tid]; Q += redQ[t*64 + tid]; }
        atomicAdd(&g_sum[sOut][tid], (double)S);
        atomicAdd(&g_sqs[sOut][tid], (double)Q);
    }
}

// ---------------- finalize BN: scale/shift from stats ------------------------
__global__ void dg_finalize(int stage, int C, double invCnt,
                            const float* __restrict__ g, const float* __restrict__ b) {
    int c = blockIdx.x * 256 + threadIdx.x;
    if (c >= C) return;
    double m = g_sum[stage][c] * invCnt;
    double v = g_sqs[stage][c] * invCnt - m * m;
    float sc = g[c] * rsqrtf((float)v + 1e-5f);
    g_scale[stage][c] = sc;
    g_shift[stage][c] = b[c] - (float)m * sc;
}

// ---------------- max over k neighbors (applies bn+lrelu) --------------------
__global__ __launch_bounds__(256) void dg_maxk(const float* __restrict__ hraw,
                                               float* __restrict__ xout, int stage) {
    int t = threadIdx.x & 63;
    int q = blockIdx.x * 4 + (threadIdx.x >> 6);
    float s = g_scale[stage][t], sh = g_shift[stage][t];
    float m = -3.4e38f;
    for (int j = 0; j < KNN; j++) {
        float v = lrelu(hraw[((size_t)q * KNN + j) * 64 + t] * s + sh);
        m = fmaxf(m, v);
    }
    xout[(size_t)q * 64 + t] = m;
}

// ---------------- concat x1|x2|x3 --------------------------------------------
__global__ void dg_cat_kernel() {
    int i = blockIdx.x * 256 + threadIdx.x;
    if (i >= ROWS * 192) return;
    int r = i / 192, c = i % 192;
    float v = (c < 64)  ? g_x1[(size_t)r * 64 + c]
            : (c < 128) ? g_x2[(size_t)r * 64 + c - 64]
                        : g_x3[(size_t)r * 64 + c - 128];
    g_cat[i] = v;
}

// ---------------- 128x128 tiled GEMM, 8x8 per thread -------------------------
// C[m,n] = sum_k actA(A[m,k]) * W[n,k]
// MODE bit0: bn(actStage)+lrelu on A; MODE bit1: add gterm[(m>>12)*Nn+n]
template <int MODE>
__global__ __launch_bounds__(256) void dg_gemm128(
    const float* __restrict__ A,
    const float* __restrict__ W, int ldw,
    float* __restrict__ C,
    int Nn, int Kk, int actStage) {
    __shared__ float As[32 * 132];
    __shared__ float Ws2[32 * 132];
    int m0 = blockIdx.y * 128, n0 = blockIdx.x * 128;
    int tid = threadIdx.x, tx = tid & 15, ty = tid >> 4;
    float acc[8][8] = {};
    for (int k0 = 0; k0 < Kk; k0 += 32) {
        int r = tid >> 1, cb = (tid & 1) * 16;
        const float4* pa = (const float4*)(A + (size_t)(m0 + r) * Kk + k0 + cb);
        const float4* pw = (const float4*)(W + (size_t)(n0 + r) * ldw + k0 + cb);
        #pragma unroll
        for (int i = 0; i < 4; i++) {
            float4 v = pa[i];
            int c = cb + i * 4;
            if (MODE & 1) {
                v.x = lrelu(g_scale[actStage][k0+c+0]*v.x + g_shift[actStage][k0+c+0]);
                v.y = lrelu(g_scale[actStage][k0+c+1]*v.y + g_shift[actStage][k0+c+1]);
                v.z = lrelu(g_scale[actStage][k0+c+2]*v.z + g_shift[actStage][k0+c+2]);
                v.w = lrelu(g_scale[actStage][k0+c+3]*v.w + g_shift[actStage][k0+c+3]);
            }
            As[(c+0)*132 + r] = v.x; As[(c+1)*132 + r] = v.y;
            As[(c+2)*132 + r] = v.z; As[(c+3)*132 + r] = v.w;
            float4 w = pw[i];
            Ws2[(c+0)*132 + r] = w.x; Ws2[(c+1)*132 + r] = w.y;
            Ws2[(c+2)*132 + r] = w.z; Ws2[(c+3)*132 + r] = w.w;
        }
        __syncthreads();
        #pragma unroll 8
        for (int k = 0; k < 32; k++) {
            float a[8], b[8];
            float4 a0 = *(const float4*)&As[k*132 + ty*8];
            float4 a1 = *(const float4*)&As[k*132 + ty*8 + 4];
            float4 b0 = *(const float4*)&Ws2[k*132 + tx*8];
            float4 b1 = *(const float4*)&Ws2[k*132 + tx*8 + 4];
            a[0]=a0.x; a[1]=a0.y; a[2]=a0.z; a[3]=a0.w;
            a[4]=a1.x; a[5]=a1.y; a[6]=a1.z; a[7]=a1.w;
            b[0]=b0.x; b[1]=b0.y; b[2]=b0.z; b[3]=b0.w;
            b[4]=b1.x; b[5]=b1.y; b[6]=b1.z; b[7]=b1.w;
            #pragma unroll
            for (int i = 0; i < 8; i++)
                #pragma unroll
                for (int j = 0; j < 8; j++)
                    acc[i][j] += a[i] * b[j];
        }
        __syncthreads();
    }
    #pragma unroll
    for (int i = 0; i < 8; i++) {
        int m = m0 + ty*8 + i;
        float v[8];
        #pragma unroll
        for (int j = 0; j < 8; j++) {
            v[j] = acc[i][j];
            if (MODE & 2) v[j] += g_gterm[(m >> 12) * Nn + n0 + tx*8 + j];
        }
        size_t rowOff = (size_t)m * Nn + n0 + tx*8;
        *(float4*)&C[rowOff]     = make_float4(v[0], v[1], v[2], v[3]);
        *(float4*)&C[rowOff + 4] = make_float4(v[4], v[5], v[6], v[7]);
    }
}

// ---------------- per-channel stats over [ROWS, C] ---------------------------
__global__ void dg_stats_point(const float* __restrict__ buf, int C, int stage) {
    int r0 = blockIdx.x * 128;
    for (int c = threadIdx.x; c < C; c += 256) {
        float s = 0.f, q = 0.f;
        for (int r = r0; r < r0 + 128; r++) {
            float v = buf[(size_t)r * C + c];
            s += v; q += v * v;
        }
        atomicAdd(&g_sum[stage][c], (double)s);
        atomicAdd(&g_sqs[stage][c], (double)q);
    }
}

// ---------------- global max pool over N (after bn6+lrelu) -------------------
__global__ __launch_bounds__(1024) void dg_gmax_kernel() {
    int b = blockIdx.y, chunk = blockIdx.x;
    int e = threadIdx.x;
    float s = g_scale[5][e], t = g_shift[5][e];
    float m = -3.4e38f;
    int n0 = chunk * 128;
    for (int n = n0; n < n0 + 128; n++) {
        float v = lrelu(s * g_h6[((size_t)(b * NP + n)) * 1024 + e] + t);
        m = fmaxf(m, v);
    }
    atomicMax(&g_gmaxEnc[b * 1024 + e], fenc(m));
}

// ---------------- gterm[b,o] = sum_e gmax[b,e] * W7[o,e] ---------------------
__global__ __launch_bounds__(512) void dg_gterm_kernel(const float* __restrict__ W7) {
    int b = blockIdx.x, o = threadIdx.x;
    float acc = 0.f;
    for (int e = 0; e < 1024; e++) {
        float v = fdec(g_gmaxEnc[b * 1024 + e]);
        acc += v * W7[(size_t)o * 1216 + e];
    }
    g_gterm[b * 512 + o] = acc;
}

// ---------------- final classifier: act8(h8) @ W9^T --------------------------
__global__ __launch_bounds__(288) void dg_final(const float* __restrict__ W9,
                                                float* __restrict__ out) {
    __shared__ float a[32 * 257];
    __shared__ float w[9 * 259];
    int tid = threadIdx.x;
    for (int l = tid; l < 2304; l += 288) {
        int o = l / 256, c = l % 256;
        w[o * 259 + c] = W9[l];
    }
    int r0 = blockIdx.x * 32;
    for (int l = tid; l < 32 * 256; l += 288) {
        int rr = l / 256, c = l % 256;
        float v = g_hB[(size_t)(r0 + rr) * 256 + c];
        a[rr * 257 + c] = lrelu(g_scale[7][c] * v + g_shift[7][c]);
    }
    __syncthreads();
    int rr = tid / 9, o = tid % 9;
    float acc = 0.f;
    #pragma unroll 16
    for (int c = 0; c < 256; c++) acc += a[rr * 257 + c] * w[o * 259 + c];
    out[(size_t)(r0 + rr) * 9 + o] = acc;
}

// ---------------- host orchestration -----------------------------------------
extern "C" void kernel_launch(void* const* d_in, const int* in_sizes, int n_in,
                              void* d_out, int out_size) {
    const float* x = (const float*)d_in[0];
    const float* W[10] = {0};
    const float* G[9] = {0};
    const float* Bp[9] = {0};
    if (n_in >= 27 && in_sizes[1] == 1) {
        for (int i = 1; i <= 9; i++) W[i] = (const float*)d_in[1 + i];
        for (int i = 1; i <= 8; i++) {
            G[i]  = (const float*)d_in[11 + 2 * (i - 1)];
            Bp[i] = (const float*)d_in[12 + 2 * (i - 1)];
        }
    } else {
        for (int i = 1; i <= 9; i++) W[i] = (const float*)d_in[i];
        for (int i = 1; i <= 8; i++) {
            G[i]  = (const float*)d_in[10 + 2 * (i - 1)];
            Bp[i] = (const float*)d_in[11 + 2 * (i - 1)];
        }
    }
    float* out = (float*)d_out;

    void* tmp;
    cudaGetSymbolAddress(&tmp, g_negd);  float* negd = (float*)tmp;
    cudaGetSymbolAddress(&tmp, g_hA);    float* hA   = (float*)tmp;
    cudaGetSymbolAddress(&tmp, g_hB);    float* hB   = (float*)tmp;
    cudaGetSymbolAddress(&tmp, g_x1);    float* x1   = (float*)tmp;
    cudaGetSymbolAddress(&tmp, g_x2);    float* x2   = (float*)tmp;
    cudaGetSymbolAddress(&tmp, g_x3);    float* x3   = (float*)tmp;
    cudaGetSymbolAddress(&tmp, g_cat);   float* cat  = (float*)tmp;
    cudaGetSymbolAddress(&tmp, g_h6);    float* h6   = (float*)tmp;

    const int SQ_SMEM = 2 * 64 * 132 * 4;                 // 67584
    const int EC_SMEM = (64 * 132 + 64 * 68) * 4;         // 51200
    cudaFuncSetAttribute(dg_sqdist128, cudaFuncAttributeMaxDynamicSharedMemorySize, SQ_SMEM);
    cudaFuncSetAttribute(dg_econv64,  cudaFuncAttributeMaxDynamicSharedMemorySize, EC_SMEM);
    cudaFuncSetAttribute(dg_econv128, cudaFuncAttributeMaxDynamicSharedMemorySize, EC_SMEM);

    const double invE = 1.0 / (double)EDGES;
    const double invR = 1.0 / (double)ROWS;
    const int EB = EDGES / 128;   // 5120 edge-tile blocks

    dg_zero_kernel<<<32, 256>>>();

    // ---- block 1 (xyz) ----
    dg_knn_small<<<ROWS, 256>>>(x);
    dg_conv1e<<<EB, 256>>>(x, W[1], hA);
    dg_finalize<<<1, 256>>>(0, 64, invE, G[1], Bp[1]);
    dg_econv64<<<EB, 256, EC_SMEM>>>(hA, hB, W[2], 0, 1);
    dg_finalize<<<1, 256>>>(1, 64, invE, G[2], Bp[2]);
    dg_maxk<<<ROWS / 4, 256>>>(hB, x1, 1);

    // ---- block 2 (x1) ----
    dg_sqdist128<<<dim3(NP / 128, NP / 128, BB), 256, SQ_SMEM>>>(x1, negd);
    dg_select_kernel<<<ROWS, 256>>>();
    dg_econv128<<<EB, 256, EC_SMEM>>>(x1, hA, W[3], 2);
    dg_finalize<<<1, 256>>>(2, 64, invE, G[3], Bp[3]);
    dg_econv64<<<EB, 256, EC_SMEM>>>(hA, hB, W[4], 2, 3);
    dg_finalize<<<1, 256>>>(3, 64, invE, G[4], Bp[4]);
    dg_maxk<<<ROWS / 4, 256>>>(hB, x2, 3);

    // ---- block 3 (x2) ----
    dg_sqdist128<<<dim3(NP / 128, NP / 128, BB), 256, SQ_SMEM>>>(x2, negd);
    dg_select_kernel<<<ROWS, 256>>>();
    dg_econv128<<<EB, 256, EC_SMEM>>>(x2, hA, W[5], 4);
    dg_finalize<<<1, 256>>>(4, 64, invE, G[5], Bp[5]);
    dg_maxk<<<ROWS / 4, 256>>>(hA, x3, 4);

    // ---- point MLPs ----
    dg_cat_kernel<<<(ROWS * 192 + 255) / 256, 256>>>();
    dg_gemm128<0><<<dim3(1024 / 128, ROWS / 128), 256>>>(cat, W[6], 192, h6, 1024, 192, -1);
    dg_stats_point<<<256, 256>>>(h6, 1024, 5);
    dg_finalize<<<4, 256>>>(5, 1024, invR, G[6], Bp[6]);
    dg_gmax_kernel<<<dim3(32, BB), 1024>>>();
    dg_gterm_kernel<<<BB, 512>>>(W[7]);
    dg_gemm128<2><<<dim3(512 / 128, ROWS / 128), 256>>>(cat, W[7] + 1024, 1216, hA, 512, 192, -1);
    dg_stats_point<<<256, 256>>>(hA, 512, 6);
    dg_finalize<<<2, 256>>>(6, 512, invR, G[7], Bp[7]);
    dg_gemm128<1><<<dim3(256 / 128, ROWS / 128), 256>>>(hA, W[8], 512, hB, 256, 512, 6);
    dg_stats_point<<<256, 256>>>(hB, 256, 7);
    dg_finalize<<<1, 256>>>(7, 256, invR, G[8], Bp[8]);
    dg_final<<<ROWS / 32, 288>>>(W[9], out);
}

// round 9
// speedup vs baseline: 1.3355x; 1.0067x over previous
#include <cuda_runtime.h>

#define BB 8
#define NP 4096
#define KNN 20
#define ROWS (BB*NP)          // 32768
#define EDGES (ROWS*KNN)      // 655360

typedef unsigned long long ull;

// ---------------- scratch (device globals; no allocations allowed) ----------
static __device__ float    g_negd[(size_t)BB * NP * NP];        // 512 MB
static __device__ int      g_idx[ROWS * KNN];
static __device__ float    g_hA[(size_t)EDGES * 64];            // 160 MB
static __device__ float    g_hB[(size_t)EDGES * 64];            // 160 MB
static __device__ float    g_x1[(size_t)ROWS * 64];
static __device__ float    g_x2[(size_t)ROWS * 64];
static __device__ float    g_x3[(size_t)ROWS * 64];
static __device__ float    g_cat[(size_t)ROWS * 192];
static __device__ float    g_h6[(size_t)ROWS * 1024];           // 128 MB
static __device__ unsigned g_gmaxEnc[BB * 1024];
static __device__ float    g_gterm[BB * 512];
static __device__ double   g_sum[8][1024];
static __device__ double   g_sqs[8][1024];
static __device__ float    g_scale[8][1024];
static __device__ float    g_shift[8][1024];

__device__ __forceinline__ float lrelu(float v) { return v > 0.f ? v : 0.2f * v; }
__device__ __forceinline__ unsigned fenc(float f) {
    unsigned u = __float_as_uint(f);
    return (u & 0x80000000u) ? ~u : (u | 0x80000000u);
}
__device__ __forceinline__ float fdec(unsigned u) {
    return (u & 0x80000000u) ? __uint_as_float(u & 0x7fffffffu) : __uint_as_float(~u);
}

// ---- packed f32x2 helpers (FFMA2/FADD2 are PTX-only on sm_103a) -------------
__device__ __forceinline__ ull dup2(float v) {
    ull r; asm("mov.b64 %0, {%1, %1};" : "=l"(r) : "f"(v)); return r;
}
__device__ __forceinline__ ull add2(ull a, ull b) {
    ull r; asm("add.rn.f32x2 %0, %1, %2;" : "=l"(r) : "l"(a), "l"(b)); return r;
}
__device__ __forceinline__ void fma2(ull& d, ull a, ull b) {
    asm("fma.rn.f32x2 %0, %1, %2, %0;" : "+l"(d) : "l"(a), "l"(b));
}
__device__ __forceinline__ void unpack2(ull p, float& lo, float& hi) {
    asm("mov.b64 {%0, %1}, %2;" : "=f"(lo), "=f"(hi) : "l"(p));
}

extern __shared__ float dsm[];

// ---------------- zero stats/atomics (must run every replay) ----------------
__global__ void dg_zero_kernel() {
    int i = blockIdx.x * 256 + threadIdx.x;
    if (i < 8192) {
        (&g_sum[0][0])[i] = 0.0;
        (&g_sqs[0][0])[i] = 0.0;
        g_gmaxEnc[i] = 0u;
    }
}

// ---------------- kNN on raw xyz: cancellation-free distances ---------------
__global__ __launch_bounds__(256) void dg_knn_small(const float* __restrict__ x) {
    int q = blockIdx.x;
    int b = q >> 12, i = q & 4095;
    const float* xb = x + (size_t)b * 3 * NP;
    __shared__ float sd[NP];
    __shared__ float rv[8];
    __shared__ int   ri[8];
    int tid = threadIdx.x, lane = tid & 31, wid = tid >> 5;
    float qx = xb[i], qy = xb[NP + i], qz = xb[2 * NP + i];
    for (int j = tid; j < NP; j += 256) {
        float dx = xb[j] - qx, dy = xb[NP + j] - qy, dz = xb[2 * NP + j] - qz;
        sd[j] = -(dx * dx + dy * dy + dz * dz);
    }
    __syncthreads();
    for (int r = 0; r < KNN; r++) {
        float bv = -3.4e38f; int bi = 0x7fffffff;
        for (int j = tid; j < NP; j += 256) {
            float v = sd[j];
            if (v > bv) { bv = v; bi = j; }
        }
        for (int s = 16; s > 0; s >>= 1) {
            float ov = __shfl_xor_sync(0xffffffffu, bv, s);
            int   oi = __shfl_xor_sync(0xffffffffu, bi, s);
            if (ov > bv || (ov == bv && oi < bi)) { bv = ov; bi = oi; }
        }
        if (lane == 0) { rv[wid] = bv; ri[wid] = bi; }
        __syncthreads();
        if (tid == 0) {
            float bbv = rv[0]; int bbi = ri[0];
            for (int w = 1; w < 8; w++)
                if (rv[w] > bbv || (rv[w] == bbv && ri[w] < bbi)) { bbv = rv[w]; bbi = ri[w]; }
            g_idx[q * KNN + r] = bbi;
            sd[bbi] = -3.4e38f;
        }
        __syncthreads();
    }
}

// ---------------- top-k selection from a precomputed neg_d row --------------
__global__ __launch_bounds__(256) void dg_select_kernel() {
    int q = blockIdx.x;
    __shared__ float sd[NP];
    __shared__ float rv[8];
    __shared__ int   ri[8];
    const float* row = g_negd + (size_t)q * NP;
    int tid = threadIdx.x, lane = tid & 31, wid = tid >> 5;
    for (int j = tid; j < NP; j += 256) sd[j] = row[j];
    __syncthreads();
    for (int r = 0; r < KNN; r++) {
        float bv = -3.4e38f; int bi = 0x7fffffff;
        for (int j = tid; j < NP; j += 256) {
            float v = sd[j];
            if (v > bv) { bv = v; bi = j; }
        }
        for (int s = 16; s > 0; s >>= 1) {
            float ov = __shfl_xor_sync(0xffffffffu, bv, s);
            int   oi = __shfl_xor_sync(0xffffffffu, bi, s);
            if (ov > bv || (ov == bv && oi < bi)) { bv = ov; bi = oi; }
        }
        if (lane == 0) { rv[wid] = bv; ri[wid] = bi; }
        __syncthreads();
        if (tid == 0) {
            float bbv = rv[0]; int bbi = ri[0];
            for (int w = 1; w < 8; w++)
                if (rv[w] > bbv || (rv[w] == bbv && ri[w] < bbi)) { bbv = rv[w]; bbi = ri[w]; }
            g_idx[q * KNN + r] = bbi;
            sd[bbi] = -3.4e38f;
        }
        __syncthreads();
    }
}

// ---------------- pairwise -||a-b||^2, 128x128 tile, f32x2 inner loop --------
// Bs holds NEGATED values so d = a + (-b) (bit-identical to a - b).
__global__ __launch_bounds__(256) void dg_sqdist128(const float* __restrict__ X,
                                                    float* __restrict__ C) {
    int bz = blockIdx.z;
    const float* A = X + (size_t)bz * NP * 64;
    float* Cb = C + (size_t)bz * NP * NP;
    float* As = dsm;              // [64][132]
    float* Bs = dsm + 64 * 132;   // [64][132] (negated)
    int m0 = blockIdx.y * 128, n0 = blockIdx.x * 128;
    int tid = threadIdx.x;
    {
        int r = tid >> 1, cb = (tid & 1) * 32;
        const float4* pa = (const float4*)(A + (size_t)(m0 + r) * 64 + cb);
        const float4* pb = (const float4*)(A + (size_t)(n0 + r) * 64 + cb);
        #pragma unroll
        for (int i = 0; i < 8; i++) {
            float4 va = pa[i], vb = pb[i];
            int c = cb + i * 4;
            As[(c+0)*132 + r] = va.x; As[(c+1)*132 + r] = va.y;
            As[(c+2)*132 + r] = va.z; As[(c+3)*132 + r] = va.w;
            Bs[(c+0)*132 + r] = -vb.x; Bs[(c+1)*132 + r] = -vb.y;
            Bs[(c+2)*132 + r] = -vb.z; Bs[(c+3)*132 + r] = -vb.w;
        }
    }
    __syncthreads();
    int tx = tid & 15, ty = tid >> 4;
    ull acc2[8][4] = {};
    const ull* BsU = (const ull*)Bs;      // row stride 66 ull
    #pragma unroll 4
    for (int k = 0; k < 64; k++) {
        float4 a0 = *(const float4*)&As[k*132 + ty*8];
        float4 a1 = *(const float4*)&As[k*132 + ty*8 + 4];
        const longlong2* pb = (const longlong2*)(BsU + (size_t)k*66 + tx*4);
        longlong2 nbA = pb[0], nbB = pb[1];
        ull nb[4] = {(ull)nbA.x, (ull)nbA.y, (ull)nbB.x, (ull)nbB.y};
        float a[8] = {a0.x, a0.y, a0.z, a0.w, a1.x, a1.y, a1.z, a1.w};
        #pragma unroll
        for (int i = 0; i < 8; i++) {
            ull ad = dup2(a[i]);
            #pragma unroll
            for (int j = 0; j < 4; j++) {
                ull d = add2(ad, nb[j]);
                fma2(acc2[i][j], d, d);
            }
        }
    }
    #pragma unroll
    for (int i = 0; i < 8; i++) {
        float v[8];
        #pragma unroll
        for (int j = 0; j < 4; j++) unpack2(acc2[i][j], v[2*j], v[2*j+1]);
        size_t rowOff = (size_t)(m0 + ty*8 + i) * NP + n0 + tx*8;
        *(float4*)&Cb[rowOff]     = make_float4(-v[0], -v[1], -v[2], -v[3]);
        *(float4*)&Cb[rowOff + 4] = make_float4(-v[4], -v[5], -v[6], -v[7]);
    }
}

// ---------------- conv1 as gather-GEMM: 128 edges x 64 out, K=6 -------------
__global__ __launch_bounds__(256) void dg_conv1e(const float* __restrict__ x,
                                                 const float* __restrict__ W1,
                                                 float* __restrict__ out) {
    __shared__ float fS[6 * 132];
    __shared__ float Ws[6 * 68];
    __shared__ int qS[128], nbS[128];
    __shared__ float redS[1024], redQ[1024];
    int e0 = blockIdx.x * 128;
    int tid = threadIdx.x;
    if (tid < 128) { int e = e0 + tid; qS[tid] = e / KNN; nbS[tid] = g_idx[e]; }
    for (int l = tid; l < 384; l += 256) {
        int o = l / 6, c = l % 6;
        Ws[c * 68 + o] = W1[l];
    }
    __syncthreads();
    for (int l = tid; l < 1024; l += 256) {
        int r = l >> 3, c = l & 7;
        if (c < 6) {
            int q = qS[r], nb = nbS[r];
            const float* xb = x + (size_t)(q >> 12) * 3 * NP;
            int qi = q & 4095;
            float v = (c < 3) ? (xb[c * NP + nb] - xb[c * NP + qi])
                              : xb[(c - 3) * NP + qi];
            fS[c * 132 + r] = v;
        }
    }
    __syncthreads();
    int tx = tid & 15, ty = tid >> 4;
    float acc[8][4] = {};
    #pragma unroll
    for (int k = 0; k < 6; k++) {
        float a[8], b[4];
        #pragma unroll
        for (int i = 0; i < 8; i++) a[i] = fS[k*132 + ty*8 + i];
        float4 bv = *(const float4*)&Ws[k*68 + tx*4];
        b[0]=bv.x; b[1]=bv.y; b[2]=bv.z; b[3]=bv.w;
        #pragma unroll
        for (int i = 0; i < 8; i++)
            #pragma unroll
            for (int j = 0; j < 4; j++)
                acc[i][j] += a[i] * b[j];
    }
    float s[4] = {}, sq[4] = {};
    #pragma unroll
    for (int i = 0; i < 8; i++) {
        size_t rowOff = (size_t)(e0 + ty*8 + i) * 64 + tx*4;
        *(float4*)&out[rowOff] = make_float4(acc[i][0], acc[i][1], acc[i][2], acc[i][3]);
        #pragma unroll
        for (int j = 0; j < 4; j++) { s[j] += acc[i][j]; sq[j] += acc[i][j]*acc[i][j]; }
    }
    #pragma unroll
    for (int j = 0; j < 4; j++) { redS[ty*64 + tx*4 + j] = s[j]; redQ[ty*64 + tx*4 + j] = sq[j]; }
    __syncthreads();
    if (tid < 64) {
        float S = 0.f, Q = 0.f;
        #pragma unroll
        for (int t = 0; t < 16; t++) { S += redS[t*64 + tid]; Q += redQ[t*64 + tid]; }
        atomicAdd(&g_sum[0][tid], (double)S);
        atomicAdd(&g_sqs[0][tid], (double)Q);
    }
}

// ---------------- edge conv 64 -> 64 as GEMM (act fused; f32x2 core) ---------
__global__ __launch_bounds__(256) void dg_econv64(const float* __restrict__ in,
                                                  float* __restrict__ out,
                                                  const float* __restrict__ W,
                                                  int sIn, int sOut) {
    float* fS = dsm;              // [64][132]
    float* Ws = dsm + 64 * 132;   // [64][68]
    __shared__ float scS[64], shS[64];
    int e0 = blockIdx.x * 128;
    int tid = threadIdx.x;
    if (tid < 64) { scS[tid] = g_scale[sIn][tid]; shS[tid] = g_shift[sIn][tid]; }
    for (int l = tid; l < 4096; l += 256) {
        int c = l >> 6, n = l & 63;
        Ws[c * 68 + n] = W[n * 64 + c];
    }
    __syncthreads();
    {
        int r = tid >> 1, cb = (tid & 1) * 32;
        const float4* p = (const float4*)(in + (size_t)(e0 + r) * 64 + cb);
        #pragma unroll
        for (int i = 0; i < 8; i++) {
            float4 v = p[i];
            int c = cb + i * 4;
            fS[(c+0)*132 + r] = lrelu(scS[c+0]*v.x + shS[c+0]);
            fS[(c+1)*132 + r] = lrelu(scS[c+1]*v.y + shS[c+1]);
            fS[(c+2)*132 + r] = lrelu(scS[c+2]*v.z + shS[c+2]);
            fS[(c+3)*132 + r] = lrelu(scS[c+3]*v.w + shS[c+3]);
        }
    }
    __syncthreads();
    int tx = tid & 15, ty = tid >> 4;
    ull acc2[8][2] = {};
    const ull* WsU = (const ull*)Ws;      // row stride 34 ull
    #pragma unroll 4
    for (int k = 0; k < 64; k++) {
        float4 a0 = *(const float4*)&fS[k*132 + ty*8];
        float4 a1 = *(const float4*)&fS[k*132 + ty*8 + 4];
        longlong2 wb = *(const longlong2*)(WsU + (size_t)k*34 + tx*2);
        ull b0 = (ull)wb.x, b1 = (ull)wb.y;
        float a[8] = {a0.x, a0.y, a0.z, a0.w, a1.x, a1.y, a1.z, a1.w};
        #pragma unroll
        for (int i = 0; i < 8; i++) {
            ull ad = dup2(a[i]);
            fma2(acc2[i][0], ad, b0);
            fma2(acc2[i][1], ad, b1);
        }
    }
    float s[4] = {}, sq[4] = {};
    #pragma unroll
    for (int i = 0; i < 8; i++) {
        float v[4];
        unpack2(acc2[i][0], v[0], v[1]);
        unpack2(acc2[i][1], v[2], v[3]);
        size_t rowOff = (size_t)(e0 + ty*8 + i) * 64 + tx*4;
        *(float4*)&out[rowOff] = make_float4(v[0], v[1], v[2], v[3]);
        #pragma unroll
        for (int j = 0; j < 4; j++) { s[j] += v[j]; sq[j] += v[j]*v[j]; }
    }
    __syncthreads();
    float* redS = fS;
    float* redQ = fS + 1024;
    #pragma unroll
    for (int j = 0; j < 4; j++) { redS[ty*64 + tx*4 + j] = s[j]; redQ[ty*64 + tx*4 + j] = sq[j]; }
    __syncthreads();
    if (tid < 64) {
        float S = 0.f, Q = 0.f;
        #pragma unroll
        for (int t = 0; t < 16; t++) { S += redS[t*64 + tid]; Q += redQ[t*64 + tid]; }
        atomicAdd(&g_sum[sOut][tid], (double)S);
        atomicAdd(&g_sqs[sOut][tid], (double)Q);
    }
}

// ---------------- edge conv 128 -> 64 as GEMM, gather, f32x2 core ------------
__global__ __launch_bounds__(256) void dg_econv128(const float* __restrict__ xin,
                                                   float* __restrict__ out,
                                                   const float* __restrict__ W,
                                                   int sOut) {
    float* fS = dsm;              // [64][132]
    float* Ws = dsm + 64 * 132;   // [64][68]
    __shared__ int qS[128], nbS[128];
    int e0 = blockIdx.x * 128;
    int tid = threadIdx.x;
    if (tid < 128) {
        int e = e0 + tid;
        int q = e / KNN;
        qS[tid] = q;
        nbS[tid] = (q >> 12) * NP + g_idx[e];
    }
    __syncthreads();
    int tx = tid & 15, ty = tid >> 4;
    ull acc2[8][2] = {};
    const ull* WsU = (const ull*)Ws;
    for (int kt = 0; kt < 2; kt++) {
        int r = tid >> 1, cb = (tid & 1) * 32;
        int q = qS[r];
        const float4* pq = (const float4*)(xin + (size_t)q * 64 + cb);
        if (kt == 0) {
            const float4* pn = (const float4*)(xin + (size_t)nbS[r] * 64 + cb);
            #pragma unroll
            for (int i = 0; i < 8; i++) {
                float4 vn = pn[i], vq = pq[i];
                int c = cb + i * 4;
                fS[(c+0)*132 + r] = vn.x - vq.x;
                fS[(c+1)*132 + r] = vn.y - vq.y;
                fS[(c+2)*132 + r] = vn.z - vq.z;
                fS[(c+3)*132 + r] = vn.w - vq.w;
            }
        } else {
            #pragma unroll
            for (int i = 0; i < 8; i++) {
                float4 vq = pq[i];
                int c = cb + i * 4;
                fS[(c+0)*132 + r] = vq.x;
                fS[(c+1)*132 + r] = vq.y;
                fS[(c+2)*132 + r] = vq.z;
                fS[(c+3)*132 + r] = vq.w;
            }
        }
        for (int l = tid; l < 4096; l += 256) {
            int c = l >> 6, n = l & 63;
            Ws[c * 68 + n] = W[n * 128 + kt * 64 + c];
        }
        __syncthreads();
        #pragma unroll 4
        for (int k = 0; k < 64; k++) {
            float4 a0 = *(const float4*)&fS[k*132 + ty*8];
            float4 a1 = *(const float4*)&fS[k*132 + ty*8 + 4];
            longlong2 wb = *(const longlong2*)(WsU + (size_t)k*34 + tx*2);
            ull b0 = (ull)wb.x, b1 = (ull)wb.y;
            float a[8] = {a0.x, a0.y, a0.z, a0.w, a1.x, a1.y, a1.z, a1.w};
            #pragma unroll
            for (int i = 0; i < 8; i++) {
                ull ad = dup2(a[i]);
                fma2(acc2[i][0], ad, b0);
                fma2(acc2[i][1], ad, b1);
            }
        }
        __syncthreads();
    }
    float s[4] = {}, sq[4] = {};
    #pragma unroll
    for (int i = 0; i < 8; i++) {
        float v[4];
        unpack2(acc2[i][0], v[0], v[1]);
        unpack2(acc2[i][1], v[2], v[3]);
        size_t rowOff = (size_t)(e0 + ty*8 + i) * 64 + tx*4;
        *(float4*)&out[rowOff] = make_float4(v[0], v[1], v[2], v[3]);
        #pragma unroll
        for (int j = 0; j < 4; j++) { s[j] += v[j]; sq[j] += v[j]*v[j]; }
    }
    float* redS = fS;
    float* redQ = fS + 1024;
    #pragma unroll
    for (int j = 0; j < 4; j++) { redS[ty*64 + tx*4 + j] = s[j]; redQ[ty*64 + tx*4 + j] = sq[j]; }
    __syncthreads();
    if (tid < 64) {
        float S = 0.f, Q = 0.f;
        #pragma unroll
        for (int t = 0; t < 16; t++) { S += redS[t*64 + tid]; Q += redQ[t*64 + tid]; }
        atomicAdd(&g_sum[sOut][tid], (double)S);
        atomicAdd(&g_sqs[sOut][tid], (double)Q);
    }
}

// ---------------- finalize BN: scale/shift from stats ------------------------
__global__ void dg_finalize(int stage, int C, double invCnt,
                            const float* __restrict__ g, const float* __restrict__ b) {
    int c = blockIdx.x * 256 + threadIdx.x;
    if (c >= C) return;
    double m = g_sum[stage][c] * invCnt;
    double v = g_sqs[stage][c] * invCnt - m * m;
    float sc = g[c] * rsqrtf((float)v + 1e-5f);
    g_scale[stage][c] = sc;
    g_shift[stage][c] = b[c] - (float)m * sc;
}

// ---------------- max over k neighbors (applies bn+lrelu) --------------------
__global__ __launch_bounds__(256) void dg_maxk(const float* __restrict__ hraw,
                                               float* __restrict__ xout, int stage) {
    int t = threadIdx.x & 63;
    int q = blockIdx.x * 4 + (threadIdx.x >> 6);
    float s = g_scale[stage][t], sh = g_shift[stage][t];
    float m = -3.4e38f;
    for (int j = 0; j < KNN; j++) {
        float v = lrelu(hraw[((size_t)q * KNN + j) * 64 + t] * s + sh);
        m = fmaxf(m, v);
    }
    xout[(size_t)q * 64 + t] = m;
}

// ---------------- concat x1|x2|x3 --------------------------------------------
__global__ void dg_cat_kernel() {
    int i = blockIdx.x * 256 + threadIdx.x;
    if (i >= ROWS * 192) return;
    int r = i / 192, c = i % 192;
    float v = (c < 64)  ? g_x1[(size_t)r * 64 + c]
            : (c < 128) ? g_x2[(size_t)r * 64 + c - 64]
                        : g_x3[(size_t)r * 64 + c - 128];
    g_cat[i] = v;
}

// ---------------- 128x128 tiled GEMM, f32x2 core -----------------------------
// C[m,n] = sum_k actA(A[m,k]) * W[n,k]
// MODE bit0: bn(actStage)+lrelu on A; MODE bit1: add gterm[(m>>12)*Nn+n]
template <int MODE>
__global__ __launch_bounds__(256) void dg_gemm128(
    const float* __restrict__ A,
    const float* __restrict__ W, int ldw,
    float* __restrict__ C,
    int Nn, int Kk, int actStage) {
    __shared__ float As[32 * 132];
    __shared__ float Ws2[32 * 132];
    int m0 = blockIdx.y * 128, n0 = blockIdx.x * 128;
    int tid = threadIdx.x, tx = tid & 15, ty = tid >> 4;
    ull acc2[8][4] = {};
    const ull* WsU = (const ull*)Ws2;     // row stride 66 ull
    for (int k0 = 0; k0 < Kk; k0 += 32) {
        int r = tid >> 1, cb = (tid & 1) * 16;
        const float4* pa = (const float4*)(A + (size_t)(m0 + r) * Kk + k0 + cb);
        const float4* pw = (const float4*)(W + (size_t)(n0 + r) * ldw + k0 + cb);
        #pragma unroll
        for (int i = 0; i < 4; i++) {
            float4 v = pa[i];
            int c = cb + i * 4;
            if (MODE & 1) {
                v.x = lrelu(g_scale[actStage][k0+c+0]*v.x + g_shift[actStage][k0+c+0]);
                v.y = lrelu(g_scale[actStage][k0+c+1]*v.y + g_shift[actStage][k0+c+1]);
                v.z = lrelu(g_scale[actStage][k0+c+2]*v.z + g_shift[actStage][k0+c+2]);
                v.w = lrelu(g_scale[actStage][k0+c+3]*v.w + g_shift[actStage][k0+c+3]);
            }
            As[(c+0)*132 + r] = v.x; As[(c+1)*132 + r] = v.y;
            As[(c+2)*132 + r] = v.z; As[(c+3)*132 + r] = v.w;
            float4 w = pw[i];
            Ws2[(c+0)*132 + r] = w.x; Ws2[(c+1)*132 + r] = w.y;
            Ws2[(c+2)*132 + r] = w.z; Ws2[(c+3)*132 + r] = w.w;
        }
        __syncthreads();
        #pragma unroll 4
        for (int k = 0; k < 32; k++) {
            float4 a0 = *(const float4*)&As[k*132 + ty*8];
            float4 a1 = *(const float4*)&As[k*132 + ty*8 + 4];
            const longlong2* pb = (const longlong2*)(WsU + (size_t)k*66 + tx*4);
            longlong2 wbA = pb[0], wbB = pb[1];
            ull wb[4] = {(ull)wbA.x, (ull)wbA.y, (ull)wbB.x, (ull)wbB.y};
            float a[8] = {a0.x, a0.y, a0.z, a0.w, a1.x, a1.y, a1.z, a1.w};
            #pragma unroll
            for (int i = 0; i < 8; i++) {
                ull ad = dup2(a[i]);
                #pragma unroll
                for (int j = 0; j < 4; j++) fma2(acc2[i][j], ad, wb[j]);
            }
        }
        __syncthreads();
    }
    #pragma unroll
    for (int i = 0; i < 8; i++) {
        int m = m0 + ty*8 + i;
        float v[8];
        #pragma unroll
        for (int j = 0; j < 4; j++) unpack2(acc2[i][j], v[2*j], v[2*j+1]);
        if (MODE & 2) {
            #pragma unroll
            for (int j = 0; j < 8; j++) v[j] += g_gterm[(m >> 12) * Nn + n0 + tx*8 + j];
        }
        size_t rowOff = (size_t)m * Nn + n0 + tx*8;
        *(float4*)&C[rowOff]     = make_float4(v[0], v[1], v[2], v[3]);
        *(float4*)&C[rowOff + 4] = make_float4(v[4], v[5], v[6], v[7]);
    }
}

// ---------------- per-channel stats over [ROWS, C] ---------------------------
__global__ void dg_stats_point(const float* __restrict__ buf, int C, int stage) {
    int r0 = blockIdx.x * 128;
    for (int c = threadIdx.x; c < C; c += 256) {
        float s = 0.f, q = 0.f;
        for (int r = r0; r < r0 + 128; r++) {
            float v = buf[(size_t)r * C + c];
            s += v; q += v * v;
        }
        atomicAdd(&g_sum[stage][c], (double)s);
        atomicAdd(&g_sqs[stage][c], (double)q);
    }
}

// ---------------- global max pool over N (after bn6+lrelu) -------------------
__global__ __launch_bounds__(1024) void dg_gmax_kernel() {
    int b = blockIdx.y, chunk = blockIdx.x;
    int e = threadIdx.x;
    float s = g_scale[5][e], t = g_shift[5][e];
    float m = -3.4e38f;
    int n0 = chunk * 128;
    for (int n = n0; n < n0 + 128; n++) {
        float v = lrelu(s * g_h6[((size_t)(b * NP + n)) * 1024 + e] + t);
        m = fmaxf(m, v);
    }
    atomicMax(&g_gmaxEnc[b * 1024 + e], fenc(m));
}

// ---------------- gterm[b,o] = sum_e gmax[b,e] * W7[o,e] ---------------------
__global__ __launch_bounds__(512) void dg_gterm_kernel(const float* __restrict__ W7) {
    int b = blockIdx.x, o = threadIdx.x;
    float acc = 0.f;
    for (int e = 0; e < 1024; e++) {
        float v = fdec(g_gmaxEnc[b * 1024 + e]);
        acc += v * W7[(size_t)o * 1216 + e];
    }
    g_gterm[b * 512 + o] = acc;
}

// ---------------- final classifier: act8(h8) @ W9^T --------------------------
__global__ __launch_bounds__(288) void dg_final(const float* __restrict__ W9,
                                                float* __restrict__ out) {
    __shared__ float a[32 * 257];
    __shared__ float w[9 * 259];
    int tid = threadIdx.x;
    for (int l = tid; l < 2304; l += 288) {
        int o = l / 256, c = l % 256;
        w[o * 259 + c] = W9[l];
    }
    int r0 = blockIdx.x * 32;
    for (int l = tid; l < 32 * 256; l += 288) {
        int rr = l / 256, c = l % 256;
        float v = g_hB[(size_t)(r0 + rr) * 256 + c];
        a[rr * 257 + c] = lrelu(g_scale[7][c] * v + g_shift[7][c]);
    }
    __syncthreads();
    int rr = tid / 9, o = tid % 9;
    float acc = 0.f;
    #pragma unroll 16
    for (int c = 0; c < 256; c++) acc += a[rr * 257 + c] * w[o * 259 + c];
    out[(size_t)(r0 + rr) * 9 + o] = acc;
}

// ---------------- host orchestration -----------------------------------------
extern "C" void kernel_launch(void* const* d_in, const int* in_sizes, int n_in,
                              void* d_out, int out_size) {
    const float* x = (const float*)d_in[0];
    const float* W[10] = {0};
    const float* G[9] = {0};
    const float* Bp[9] = {0};
    if (n_in >= 27 && in_sizes[1] == 1) {
        for (int i = 1; i <= 9; i++) W[i] = (const float*)d_in[1 + i];
        for (int i = 1; i <= 8; i++) {
            G[i]  = (const float*)d_in[11 + 2 * (i - 1)];
            Bp[i] = (const float*)d_in[12 + 2 * (i - 1)];
        }
    } else {
        for (int i = 1; i <= 9; i++) W[i] = (const float*)d_in[i];
        for (int i = 1; i <= 8; i++) {
            G[i]  = (const float*)d_in[10 + 2 * (i - 1)];
            Bp[i] = (const float*)d_in[11 + 2 * (i - 1)];
        }
    }
    float* out = (float*)d_out;

    void* tmp;
    cudaGetSymbolAddress(&tmp, g_negd);  float* negd = (float*)tmp;
    cudaGetSymbolAddress(&tmp, g_hA);    float* hA   = (float*)tmp;
    cudaGetSymbolAddress(&tmp, g_hB);    float* hB   = (float*)tmp;
    cudaGetSymbolAddress(&tmp, g_x1);    float* x1   = (float*)tmp;
    cudaGetSymbolAddress(&tmp, g_x2);    float* x2   = (float*)tmp;
    cudaGetSymbolAddress(&tmp, g_x3);    float* x3   = (float*)tmp;
    cudaGetSymbolAddress(&tmp, g_cat);   float* cat  = (float*)tmp;
    cudaGetSymbolAddress(&tmp, g_h6);    float* h6   = (float*)tmp;

    const int SQ_SMEM = 2 * 64 * 132 * 4;                 // 67584
    const int EC_SMEM = (64 * 132 + 64 * 68) * 4;         // 51200
    cudaFuncSetAttribute(dg_sqdist128, cudaFuncAttributeMaxDynamicSharedMemorySize, SQ_SMEM);
    cudaFuncSetAttribute(dg_econv64,  cudaFuncAttributeMaxDynamicSharedMemorySize, EC_SMEM);
    cudaFuncSetAttribute(dg_econv128, cudaFuncAttributeMaxDynamicSharedMemorySize, EC_SMEM);

    const double invE = 1.0 / (double)EDGES;
    const double invR = 1.0 / (double)ROWS;
    const int EB = EDGES / 128;   // 5120 edge-tile blocks

    dg_zero_kernel<<<32, 256>>>();

    // ---- block 1 (xyz) ----
    dg_knn_small<<<ROWS, 256>>>(x);
    dg_conv1e<<<EB, 256>>>(x, W[1], hA);
    dg_finalize<<<1, 256>>>(0, 64, invE, G[1], Bp[1]);
    dg_econv64<<<EB, 256, EC_SMEM>>>(hA, hB, W[2], 0, 1);
    dg_finalize<<<1, 256>>>(1, 64, invE, G[2], Bp[2]);
    dg_maxk<<<ROWS / 4, 256>>>(hB, x1, 1);

    // ---- block 2 (x1) ----
    dg_sqdist128<<<dim3(NP / 128, NP / 128, BB), 256, SQ_SMEM>>>(x1, negd);
    dg_select_kernel<<<ROWS, 256>>>();
    dg_econv128<<<EB, 256, EC_SMEM>>>(x1, hA, W[3], 2);
    dg_finalize<<<1, 256>>>(2, 64, invE, G[3], Bp[3]);
    dg_econv64<<<EB, 256, EC_SMEM>>>(hA, hB, W[4], 2, 3);
    dg_finalize<<<1, 256>>>(3, 64, invE, G[4], Bp[4]);
    dg_maxk<<<ROWS / 4, 256>>>(hB, x2, 3);

    // ---- block 3 (x2) ----
    dg_sqdist128<<<dim3(NP / 128, NP / 128, BB), 256, SQ_SMEM>>>(x2, negd);
    dg_select_kernel<<<ROWS, 256>>>();
    dg_econv128<<<EB, 256, EC_SMEM>>>(x2, hA, W[5], 4);
    dg_finalize<<<1, 256>>>(4, 64, invE, G[5], Bp[5]);
    dg_maxk<<<ROWS / 4, 256>>>(hA, x3, 4);

    // ---- point MLPs ----
    dg_cat_kernel<<<(ROWS * 192 + 255) / 256, 256>>>();
    dg_gemm128<0><<<dim3(1024 / 128, ROWS / 128), 256>>>(cat, W[6], 192, h6, 1024, 192, -1);
    dg_stats_point<<<256, 256>>>(h6, 1024, 5);
    dg_finalize<<<4, 256>>>(5, 1024, invR, G[6], Bp[6]);
    dg_gmax_kernel<<<dim3(32, BB), 1024>>>();
    dg_gterm_kernel<<<BB, 512>>>(W[7]);
    dg_gemm128<2><<<dim3(512 / 128, ROWS / 128), 256>>>(cat, W[7] + 1024, 1216, hA, 512, 192, -1);
    dg_stats_point<<<256, 256>>>(hA, 512, 6);
    dg_finalize<<<2, 256>>>(6, 512, invR, G[7], Bp[7]);
    dg_gemm128<1><<<dim3(256 / 128, ROWS / 128), 256>>>(hA, W[8], 512, hB, 256, 512, 6);
    dg_stats_point<<<256, 256>>>(hB, 256, 7);
    dg_finalize<<<1, 256>>>(7, 256, invR, G[8], Bp[8]);
    dg_final<<<ROWS / 32, 288>>>(W[9], out);
}